// round 2
// baseline (speedup 1.0000x reference)
#include <cuda_runtime.h>
#include <math.h>

#define SN    255
#define BATCH 64
#define EMB   200
#define HID   300
#define NROWS (SN * BATCH)   // 16320
#define WXC   1200           // 900 (iou) + 300 (f)

// Scratch (device globals; no allocation in kernel_launch)
__device__ float g_wx[NROWS * WXC];   // per (node,batch): [iou(900) | f(300)] pre-activations (x-part + bias)
__device__ float g_H [NROWS * HID];
__device__ float g_C [NROWS * HID];
__device__ float g_FC[NROWS * HID];   // f_child * C_child, stored at child position

__device__ __forceinline__ float sigmoidf(float x) { return 1.0f / (1.0f + expf(-x)); }

// ---------------------------------------------------------------------------
// Embed gather + GEMM: wx[row, 0:900]  = embed[x[row]] @ W_iou + b_iou
//                      wx[row,900:1200]= embed[x[row]] @ W_f   + b_f
// M=16320, K=200, N=1200. 64x64 tile, BK=16, 256 threads, 4x4 micro-tile.
// ---------------------------------------------------------------------------
__global__ __launch_bounds__(256) void embed_gemm_kernel(
    const int*   __restrict__ x,
    const float* __restrict__ embed,
    const float* __restrict__ W_iou,
    const float* __restrict__ W_f,
    const float* __restrict__ b_iou,
    const float* __restrict__ b_f)
{
    __shared__ float As[16][65];
    __shared__ float Bs[16][65];
    __shared__ int   toks[64];

    const int tid     = threadIdx.x;
    const int rowBase = blockIdx.x * 64;   // grid.x = 255, exact
    const int colBase = blockIdx.y * 64;   // grid.y = 19 (covers 1200 w/ bounds)

    if (tid < 64) toks[tid] = x[rowBase + tid];
    __syncthreads();

    const int tx = tid & 15, ty = tid >> 4;
    float acc[4][4] = {};

    for (int k0 = 0; k0 < EMB; k0 += 16) {
        #pragma unroll
        for (int idx = tid; idx < 1024; idx += 256) {
            int m = idx >> 4, k = idx & 15;
            int kg = k0 + k;
            As[k][m] = (kg < EMB) ? embed[toks[m] * EMB + kg] : 0.0f;
        }
        #pragma unroll
        for (int idx = tid; idx < 1024; idx += 256) {
            int k = idx >> 6, n = idx & 63;
            int kg = k0 + k, ng = colBase + n;
            float v = 0.0f;
            if (kg < EMB && ng < WXC)
                v = (ng < 900) ? W_iou[kg * 900 + ng] : W_f[kg * 300 + (ng - 900)];
            Bs[k][n] = v;
        }
        __syncthreads();
        #pragma unroll
        for (int k = 0; k < 16; ++k) {
            float a[4], b[4];
            #pragma unroll
            for (int i = 0; i < 4; ++i) a[i] = As[k][ty * 4 + i];
            #pragma unroll
            for (int j = 0; j < 4; ++j) b[j] = Bs[k][tx * 4 + j];
            #pragma unroll
            for (int i = 0; i < 4; ++i)
                #pragma unroll
                for (int j = 0; j < 4; ++j)
                    acc[i][j] = fmaf(a[i], b[j], acc[i][j]);
        }
        __syncthreads();
    }

    #pragma unroll
    for (int i = 0; i < 4; ++i) {
        int row = rowBase + ty * 4 + i;
        #pragma unroll
        for (int j = 0; j < 4; ++j) {
            int col = colBase + tx * 4 + j;
            if (col < WXC) {
                float bias = (col < 900) ? b_iou[col] : b_f[col - 900];
                g_wx[row * WXC + col] = acc[i][j] + bias;
            }
        }
    }
}

// ---------------------------------------------------------------------------
// Leaf nodes (depth 7, nodes 127..254): iou = wx_iou; c = sig(i)*tanh(u);
// h = sig(o)*tanh(c). One block per (node,batch) row, 320 threads (n<300).
// ---------------------------------------------------------------------------
__global__ __launch_bounds__(320) void leaf_kernel()
{
    const int row = 127 * BATCH + blockIdx.x;   // grid.x = 128*64 = 8192
    const int n   = threadIdx.x;
    if (n < HID) {
        const float* wx = g_wx + row * WXC;
        float iv = sigmoidf(wx[n]);
        float ov = sigmoidf(wx[300 + n]);
        float uv = tanhf(wx[600 + n]);
        float c  = iv * uv;
        float h  = ov * tanhf(c);
        g_C[row * HID + n] = c;
        g_H[row * HID + n] = h;
    }
}

// ---------------------------------------------------------------------------
// F kernel (children at depth d+1 of parents at depth d):
//   P = H_child @ U_f; f = sigmoid(wx_f[parent] + P); FC_child = f * C_child
// One block = one child node (64 batch rows) x 64 output cols (grid.y=5).
// ---------------------------------------------------------------------------
__global__ __launch_bounds__(256) void f_kernel(const float* __restrict__ U_f, int c0)
{
    __shared__ float As[16][65];
    __shared__ float Bs[16][65];

    const int tid     = threadIdx.x;
    const int node    = c0 + blockIdx.x;
    const int rbase   = node * BATCH;
    const int colBase = blockIdx.y * 64;
    const int tx = tid & 15, ty = tid >> 4;

    float acc[4][4] = {};

    for (int k0 = 0; k0 < HID; k0 += 16) {
        #pragma unroll
        for (int idx = tid; idx < 1024; idx += 256) {
            int m = idx >> 4, k = idx & 15;
            int kg = k0 + k;
            As[k][m] = (kg < HID) ? g_H[(rbase + m) * HID + kg] : 0.0f;
        }
        #pragma unroll
        for (int idx = tid; idx < 1024; idx += 256) {
            int k = idx >> 6, n = idx & 63;
            int kg = k0 + k, ng = colBase + n;
            Bs[k][n] = (kg < HID && ng < HID) ? U_f[kg * HID + ng] : 0.0f;
        }
        __syncthreads();
        #pragma unroll
        for (int k = 0; k < 16; ++k) {
            float a[4], b[4];
            #pragma unroll
            for (int i = 0; i < 4; ++i) a[i] = As[k][ty * 4 + i];
            #pragma unroll
            for (int j = 0; j < 4; ++j) b[j] = Bs[k][tx * 4 + j];
            #pragma unroll
            for (int i = 0; i < 4; ++i)
                #pragma unroll
                for (int j = 0; j < 4; ++j)
                    acc[i][j] = fmaf(a[i], b[j], acc[i][j]);
        }
        __syncthreads();
    }

    const int p = (node - 1) >> 1;
    #pragma unroll
    for (int i = 0; i < 4; ++i) {
        int b = ty * 4 + i;
        #pragma unroll
        for (int j = 0; j < 4; ++j) {
            int n = colBase + tx * 4 + j;
            if (n < HID) {
                float wxf = g_wx[(p * BATCH + b) * WXC + 900 + n];
                float f   = sigmoidf(acc[i][j] + wxf);
                int   ridx = (rbase + b) * HID + n;
                g_FC[ridx] = f * g_C[ridx];
            }
        }
    }
}

// ---------------------------------------------------------------------------
// G kernel (parents at depth d):
//   h_sum = H[2p+1] + H[2p+2];  acc_g = h_sum @ U_iou[:, g*300 : g*300+300]
//   i = sig(acc0+wx_i); o = sig(acc1+wx_o); u = tanh(acc2+wx_u)
//   c = i*u + FC[2p+1]+FC[2p+2];  h = o*tanh(c);  write H[p], C[p]
// One block = one parent node (64 batch rows) x 64 cols (grid.y=5),
// 3 accumulator groups (i/o/u) per thread.
// ---------------------------------------------------------------------------
__global__ __launch_bounds__(256) void g_kernel(const float* __restrict__ U_iou, int p0)
{
    __shared__ float As[16][65];
    __shared__ float Bs[3][16][65];

    const int tid     = threadIdx.x;
    const int p       = p0 + blockIdx.x;
    const int colBase = blockIdx.y * 64;
    const int lc = 2 * p + 1, rc = 2 * p + 2;
    const int tx = tid & 15, ty = tid >> 4;

    float acc[3][4][4] = {};

    for (int k0 = 0; k0 < HID; k0 += 16) {
        #pragma unroll
        for (int idx = tid; idx < 1024; idx += 256) {
            int m = idx >> 4, k = idx & 15;
            int kg = k0 + k;
            float v = 0.0f;
            if (kg < HID)
                v = g_H[(lc * BATCH + m) * HID + kg] + g_H[(rc * BATCH + m) * HID + kg];
            As[k][m] = v;
        }
        #pragma unroll
        for (int idx = tid; idx < 3072; idx += 256) {
            int g = idx >> 10;
            int r = idx & 1023;
            int k = r >> 6, n = r & 63;
            int kg = k0 + k, ng = colBase + n;
            Bs[g][k][n] = (kg < HID && ng < HID) ? U_iou[kg * 900 + g * 300 + ng] : 0.0f;
        }
        __syncthreads();
        #pragma unroll
        for (int k = 0; k < 16; ++k) {
            float a[4], b[3][4];
            #pragma unroll
            for (int i = 0; i < 4; ++i) a[i] = As[k][ty * 4 + i];
            #pragma unroll
            for (int g = 0; g < 3; ++g)
                #pragma unroll
                for (int j = 0; j < 4; ++j) b[g][j] = Bs[g][k][tx * 4 + j];
            #pragma unroll
            for (int g = 0; g < 3; ++g)
                #pragma unroll
                for (int i = 0; i < 4; ++i)
                    #pragma unroll
                    for (int j = 0; j < 4; ++j)
                        acc[g][i][j] = fmaf(a[i], b[g][j], acc[g][i][j]);
        }
        __syncthreads();
    }

    #pragma unroll
    for (int i = 0; i < 4; ++i) {
        int b = ty * 4 + i;
        #pragma unroll
        for (int j = 0; j < 4; ++j) {
            int n = colBase + tx * 4 + j;
            if (n < HID) {
                const float* wxr = g_wx + (p * BATCH + b) * WXC;
                float iv = sigmoidf(acc[0][i][j] + wxr[n]);
                float ov = sigmoidf(acc[1][i][j] + wxr[300 + n]);
                float uv = tanhf  (acc[2][i][j] + wxr[600 + n]);
                float fc = g_FC[(lc * BATCH + b) * HID + n]
                         + g_FC[(rc * BATCH + b) * HID + n];
                float c  = iv * uv + fc;
                float h  = ov * tanhf(c);
                int   o  = (p * BATCH + b) * HID + n;
                g_C[o] = c;
                g_H[o] = h;
            }
        }
    }
}

// ---------------------------------------------------------------------------
// Output: logits = H[root] @ W_out + b_out; log_softmax over 2 classes.
// ---------------------------------------------------------------------------
__global__ __launch_bounds__(64) void out_kernel(
    const float* __restrict__ W_out, const float* __restrict__ b_out,
    float* __restrict__ out)
{
    const int b = threadIdx.x;       // 64 threads
    const float* h = g_H + b * HID;  // node 0 rows are rows 0..63
    float l0 = b_out[0], l1 = b_out[1];
    #pragma unroll 4
    for (int k = 0; k < HID; ++k) {
        float hv = h[k];
        l0 = fmaf(hv, W_out[k * 2 + 0], l0);
        l1 = fmaf(hv, W_out[k * 2 + 1], l1);
    }
    float m   = fmaxf(l0, l1);
    float lse = m + logf(expf(l0 - m) + expf(l1 - m));
    out[b * 2 + 0] = l0 - lse;
    out[b * 2 + 1] = l1 - lse;
}

// ---------------------------------------------------------------------------
extern "C" void kernel_launch(void* const* d_in, const int* in_sizes, int n_in,
                              void* d_out, int out_size)
{
    (void)in_sizes; (void)n_in; (void)out_size;
    const int*   x     = (const int*)  d_in[0];
    // d_in[1] = parent, d_in[2] = depth: complete binary tree, computed analytically
    const float* embed = (const float*)d_in[3];
    const float* W_iou = (const float*)d_in[4];
    const float* U_iou = (const float*)d_in[5];
    const float* b_iou = (const float*)d_in[6];
    const float* W_f   = (const float*)d_in[7];
    const float* U_f   = (const float*)d_in[8];
    const float* b_f   = (const float*)d_in[9];
    const float* W_out = (const float*)d_in[10];
    const float* b_out = (const float*)d_in[11];

    embed_gemm_kernel<<<dim3(SN, 19), 256>>>(x, embed, W_iou, W_f, b_iou, b_f);
    leaf_kernel<<<128 * BATCH, 320>>>();

    for (int d = 6; d >= 0; --d) {
        int np = 1 << d;        // parents at depth d
        int p0 = np - 1;
        int c0 = 2 * np - 1;    // first child (depth d+1)
        int nc = 2 * np;
        f_kernel<<<dim3(nc, 5), 256>>>(U_f, c0);
        g_kernel<<<dim3(np, 5), 256>>>(U_iou, p0);
    }

    out_kernel<<<1, 64>>>(W_out, b_out, (float*)d_out);
}

// round 3
// speedup vs baseline: 2.4303x; 2.4303x over previous
#include <cuda_runtime.h>
#include <math.h>
#include <stdint.h>

#define SN    255
#define B_    64
#define EMB   200
#define HID   300
#define NROWS (SN * B_)     // 16320
#define NC    1200          // concat cols: [iou(900) | f(300)]
#define NPAD  1216          // 19 * 64
#define KP_E  208           // EMB padded to mult of 16
#define KP_U  304           // HID padded to mult of 16

// ---- device scratch (no allocation in kernel_launch) ----
__device__ float    g_wx[NROWS * NC];      // x-part preacts + bias, all nodes
__device__ float    g_H [NROWS * HID];
__device__ float    g_C [NROWS * HID];
__device__ float    g_T [8192 * NC];       // per-level child GEMM out (max nc*64 rows)
__device__ uint32_t g_Bw[NPAD * KP_E];     // tf32 [W_iou|W_f], n-major [n][k]
__device__ uint32_t g_Bu[NPAD * KP_U];     // tf32 [U_iou|U_f], n-major [n][k]
__device__ float    g_bias[NC];            // [b_iou|b_f]

__device__ __forceinline__ float sigmoidf(float x) { return 1.0f / (1.0f + expf(-x)); }
__device__ __forceinline__ uint32_t f2tf(float x) {
    uint32_t u; asm("cvt.rna.tf32.f32 %0, %1;" : "=r"(u) : "f"(x)); return u;
}

// ---------------------------------------------------------------------------
// Prep: build tf32 B matrices (n-major, zero padded) + concat bias.
// ---------------------------------------------------------------------------
__global__ void prep_kernel(const float* __restrict__ W_iou, const float* __restrict__ W_f,
                            const float* __restrict__ U_iou, const float* __restrict__ U_f,
                            const float* __restrict__ b_iou, const float* __restrict__ b_f)
{
    int idx = blockIdx.x * blockDim.x + threadIdx.x;
    if (idx < NPAD * KP_E) {
        int n = idx / KP_E, k = idx % KP_E;
        float v = 0.0f;
        if (n < NC && k < EMB) v = (n < 900) ? W_iou[k * 900 + n] : W_f[k * 300 + (n - 900)];
        g_Bw[idx] = f2tf(v);
    }
    if (idx < NPAD * KP_U) {
        int n = idx / KP_U, k = idx % KP_U;
        float v = 0.0f;
        if (n < NC && k < HID) v = (n < 900) ? U_iou[k * 900 + n] : U_f[k * 300 + (n - 900)];
        g_Bu[idx] = f2tf(v);
    }
    if (idx < NC) g_bias[idx] = (idx < 900) ? b_iou[idx] : b_f[idx - 900];
}

// ---------------------------------------------------------------------------
// tf32 tensor-core GEMM, BM=64 BN=64 BK=16, 128 threads (4 warps, 2x2 of 32x32).
// MODE 0: A = embed[x[rowBase+m]] (K=200), B=g_Bw, C=g_wx (+bias)
// MODE 1: A = g_H rows from node c0   (K=300), B=g_Bu, C=g_T
// ---------------------------------------------------------------------------
template<int MODE>
__global__ __launch_bounds__(128) void gemm_tf32(
    const float* __restrict__ embedTab, const int* __restrict__ xg, int c0)
{
    constexpr int KSRC = (MODE == 0) ? EMB : HID;
    constexpr int KPAD = (MODE == 0) ? KP_E : KP_U;

    __shared__ __align__(16) uint32_t As[64][20];
    __shared__ __align__(16) uint32_t Bs[64][20];   // [n][k]
    __shared__ const float* arows[64];

    const int tid = threadIdx.x;
    const int rowBase = blockIdx.x * 64;
    const int colBase = blockIdx.y * 64;

    if (tid < 64) {
        if (MODE == 0)
            arows[tid] = embedTab + (size_t)xg[rowBase + tid] * EMB;
        else
            arows[tid] = g_H + (size_t)(c0 * B_ + rowBase + tid) * HID;
    }
    __syncthreads();

    const int lane = tid & 31, warp = tid >> 5;
    const int wm = (warp & 1) << 5, wn = (warp >> 1) << 5;
    const int tg = lane >> 2, tk = lane & 3;

    float acc[2][4][4];
    #pragma unroll
    for (int a = 0; a < 2; ++a)
        #pragma unroll
        for (int b = 0; b < 4; ++b)
            #pragma unroll
            for (int c = 0; c < 4; ++c) acc[a][b][c] = 0.0f;

    const int a_m  = tid >> 1;
    const int a_kq = (tid & 1) << 3;
    const int b_n  = tid >> 1;
    const int b_kq = (tid & 1) << 3;
    const uint32_t* Bg = (MODE == 0) ? g_Bw : g_Bu;
    const uint32_t* brow = Bg + (size_t)(colBase + b_n) * KPAD;
    const float* arow = arows[a_m];

    for (int k0 = 0; k0 < KPAD; k0 += 16) {
        // fill A (fp32 -> tf32) and B tiles
        #pragma unroll
        for (int q = 0; q < 2; ++q) {
            int kg = k0 + a_kq + q * 4;
            float4 v;
            if (kg + 3 < KSRC) v = *(const float4*)(arow + kg);
            else {
                v.x = (kg + 0 < KSRC) ? arow[kg + 0] : 0.0f;
                v.y = (kg + 1 < KSRC) ? arow[kg + 1] : 0.0f;
                v.z = (kg + 2 < KSRC) ? arow[kg + 2] : 0.0f;
                v.w = (kg + 3 < KSRC) ? arow[kg + 3] : 0.0f;
            }
            uint4 u = make_uint4(f2tf(v.x), f2tf(v.y), f2tf(v.z), f2tf(v.w));
            *(uint4*)&As[a_m][a_kq + q * 4] = u;
            uint4 w = *(const uint4*)(brow + k0 + b_kq + q * 4);
            *(uint4*)&Bs[b_n][b_kq + q * 4] = w;
        }
        __syncthreads();

        #pragma unroll
        for (int s = 0; s < 2; ++s) {
            const int kb = s << 3;
            uint32_t af[2][4], bf[4][2];
            #pragma unroll
            for (int mf = 0; mf < 2; ++mf) {
                int r = wm + (mf << 4) + tg;
                af[mf][0] = As[r][kb + tk];
                af[mf][1] = As[r + 8][kb + tk];
                af[mf][2] = As[r][kb + tk + 4];
                af[mf][3] = As[r + 8][kb + tk + 4];
            }
            #pragma unroll
            for (int nf = 0; nf < 4; ++nf) {
                int cc = wn + (nf << 3) + tg;
                bf[nf][0] = Bs[cc][kb + tk];
                bf[nf][1] = Bs[cc][kb + tk + 4];
            }
            #pragma unroll
            for (int mf = 0; mf < 2; ++mf)
                #pragma unroll
                for (int nf = 0; nf < 4; ++nf)
                    asm("mma.sync.aligned.m16n8k8.row.col.f32.tf32.tf32.f32 "
                        "{%0,%1,%2,%3},{%4,%5,%6,%7},{%8,%9},{%0,%1,%2,%3};"
                        : "+f"(acc[mf][nf][0]), "+f"(acc[mf][nf][1]),
                          "+f"(acc[mf][nf][2]), "+f"(acc[mf][nf][3])
                        : "r"(af[mf][0]), "r"(af[mf][1]), "r"(af[mf][2]), "r"(af[mf][3]),
                          "r"(bf[nf][0]), "r"(bf[nf][1]));
        }
        __syncthreads();
    }

    float* Cout = (MODE == 0) ? g_wx : g_T;
    #pragma unroll
    for (int mf = 0; mf < 2; ++mf) {
        #pragma unroll
        for (int nf = 0; nf < 4; ++nf) {
            int row = rowBase + wm + (mf << 4) + tg;
            int col = colBase + wn + (nf << 3) + (tk << 1);
            if (col < NC) {
                float b0 = 0.0f, b1 = 0.0f;
                if (MODE == 0) { b0 = g_bias[col]; b1 = g_bias[col + 1]; }
                float* o0 = Cout + (size_t)row * NC + col;
                float* o8 = Cout + (size_t)(row + 8) * NC + col;
                o0[0] = acc[mf][nf][0] + b0;
                o0[1] = acc[mf][nf][1] + b1;
                o8[0] = acc[mf][nf][2] + b0;
                o8[1] = acc[mf][nf][3] + b1;
            }
        }
    }
}

// ---------------------------------------------------------------------------
// Leaves (nodes 127..254): c = sig(i)*tanh(u); h = sig(o)*tanh(c)
// ---------------------------------------------------------------------------
__global__ void leaf_kernel()
{
    int idx = blockIdx.x * blockDim.x + threadIdx.x;
    if (idx >= 128 * B_ * HID) return;
    int n = idx % HID;
    int r = idx / HID;
    int row = 127 * B_ + r;
    const float* wx = g_wx + (size_t)row * NC;
    float iv = sigmoidf(wx[n]);
    float ov = sigmoidf(wx[300 + n]);
    float uv = tanhf(wx[600 + n]);
    float c = iv * uv;
    g_C[(size_t)row * HID + n] = c;
    g_H[(size_t)row * HID + n] = ov * tanhf(c);
}

// ---------------------------------------------------------------------------
// Per-level combine: parents p0..p0+np-1.
// T row for child c is ((c - c0)*64 + b), c0 = 2*p0+1.
// ---------------------------------------------------------------------------
__global__ void level_pw(int p0, int np)
{
    int idx = blockIdx.x * blockDim.x + threadIdx.x;
    int tot = np * B_ * HID;
    if (idx >= tot) return;
    int n = idx % HID;
    int r = idx / HID;
    int b = r % B_;
    int pi = r / B_;
    int p = p0 + pi;

    const float* wx = g_wx + (size_t)(p * B_ + b) * NC;
    const float* Tl = g_T + (size_t)((2 * pi) * B_ + b) * NC;
    const float* Tr = g_T + (size_t)((2 * pi + 1) * B_ + b) * NC;

    float iv = sigmoidf(wx[n]       + Tl[n]       + Tr[n]);
    float ov = sigmoidf(wx[300 + n] + Tl[300 + n] + Tr[300 + n]);
    float uv = tanhf   (wx[600 + n] + Tl[600 + n] + Tr[600 + n]);
    float fl = sigmoidf(wx[900 + n] + Tl[900 + n]);
    float fr = sigmoidf(wx[900 + n] + Tr[900 + n]);

    int lc = 2 * p + 1, rc = 2 * p + 2;
    float fc = fl * g_C[(size_t)(lc * B_ + b) * HID + n]
             + fr * g_C[(size_t)(rc * B_ + b) * HID + n];
    float c = iv * uv + fc;
    float h = ov * tanhf(c);
    g_C[(size_t)(p * B_ + b) * HID + n] = c;
    g_H[(size_t)(p * B_ + b) * HID + n] = h;
}

// ---------------------------------------------------------------------------
// Output head: logits = H[root] @ W_out + b_out; log_softmax (2 classes).
// ---------------------------------------------------------------------------
__global__ __launch_bounds__(64) void out_kernel(
    const float* __restrict__ W_out, const float* __restrict__ b_out,
    float* __restrict__ out)
{
    const int b = threadIdx.x;
    const float* h = g_H + (size_t)b * HID;   // node 0 rows
    float l0 = b_out[0], l1 = b_out[1];
    #pragma unroll 4
    for (int k = 0; k < HID; ++k) {
        float hv = h[k];
        l0 = fmaf(hv, W_out[k * 2 + 0], l0);
        l1 = fmaf(hv, W_out[k * 2 + 1], l1);
    }
    float m   = fmaxf(l0, l1);
    float lse = m + logf(expf(l0 - m) + expf(l1 - m));
    out[b * 2 + 0] = l0 - lse;
    out[b * 2 + 1] = l1 - lse;
}

// ---------------------------------------------------------------------------
extern "C" void kernel_launch(void* const* d_in, const int* in_sizes, int n_in,
                              void* d_out, int out_size)
{
    (void)in_sizes; (void)n_in; (void)out_size;
    const int*   x     = (const int*)  d_in[0];
    const float* embed = (const float*)d_in[3];
    const float* W_iou = (const float*)d_in[4];
    const float* U_iou = (const float*)d_in[5];
    const float* b_iou = (const float*)d_in[6];
    const float* W_f   = (const float*)d_in[7];
    const float* U_f   = (const float*)d_in[8];
    const float* b_f   = (const float*)d_in[9];
    const float* W_out = (const float*)d_in[10];
    const float* b_out = (const float*)d_in[11];

    prep_kernel<<<(NPAD * KP_U + 255) / 256, 256>>>(W_iou, W_f, U_iou, U_f, b_iou, b_f);

    // wx = [emb@W_iou + b_iou | emb@W_f + b_f] for all 16320 rows
    gemm_tf32<0><<<dim3(SN, 19), 128>>>(embed, x, 0);

    leaf_kernel<<<(128 * B_ * HID + 255) / 256, 256>>>();

    for (int d = 6; d >= 0; --d) {
        int np = 1 << d;
        int p0 = np - 1;
        int c0 = 2 * np - 1;
        int nc = 2 * np;
        // T = H[children] @ [U_iou | U_f]
        gemm_tf32<1><<<dim3(nc, 19), 128>>>(embed, x, c0);
        level_pw<<<(np * B_ * HID + 255) / 256, 256>>>(p0, np);
    }

    out_kernel<<<1, 64>>>(W_out, b_out, (float*)d_out);
}